// round 2
// baseline (speedup 1.0000x reference)
#include <cuda_runtime.h>
#include <math.h>

#define N_NODES 100000
#define N_EDGES 1600000
#define N_GRAPHS 64
#define D 128
#define DV4 32  // D/4 float4 per row

// ---------------- device scratch (static, allocation-free) ----------------
__device__ float g_x[N_NODES * D];     // current node features, pre-scaled by norm_src
__device__ float g_agg[N_NODES * D];   // aggregation output
__device__ int   g_indeg[N_NODES];
__device__ int   g_outdeg[N_NODES];
__device__ int   g_cursor[N_NODES];
__device__ float g_ns[N_NODES];        // rsqrt(out_deg)
__device__ float g_nd[N_NODES];        // rsqrt(in_deg)
__device__ float g_c1[N_NODES];        // nd*ns (folded row scale for GEMM input)
__device__ int   g_rowptr[N_NODES + 1];
__device__ int   g_csrsrc[N_EDGES];    // src node ids grouped by dst
__device__ float g_w5f[D];             // W5 @ fc_w
__device__ float g_bf;                 // b5 . fc_w
__device__ float g_p[N_NODES];         // per-node scalar logit contribution

// ---------------- CSR build ----------------
__global__ void k_zero() {
    int i = blockIdx.x * blockDim.x + threadIdx.x;
    if (i < N_NODES) { g_indeg[i] = 0; g_outdeg[i] = 0; g_cursor[i] = 0; }
}

__global__ void k_degree(const int* __restrict__ src, const int* __restrict__ dst) {
    int e = blockIdx.x * blockDim.x + threadIdx.x;
    if (e < N_EDGES) {
        atomicAdd(&g_outdeg[src[e]], 1);
        atomicAdd(&g_indeg[dst[e]], 1);
    }
}

__global__ void k_norms() {
    int i = blockIdx.x * blockDim.x + threadIdx.x;
    if (i < N_NODES) {
        float od = (float)max(g_outdeg[i], 1);
        float id = (float)max(g_indeg[i], 1);
        float ns = rsqrtf(od);
        float nd = rsqrtf(id);
        g_ns[i] = ns; g_nd[i] = nd; g_c1[i] = ns * nd;
    }
}

// single-block exclusive scan of g_indeg -> g_rowptr
__global__ void k_scan() {
    __shared__ int ssum[1024];
    int t = threadIdx.x;
    const int CH = (N_NODES + 1023) / 1024;  // 98
    int start = t * CH;
    int end = min(start + CH, N_NODES);
    int s = 0;
    for (int i = start; i < end; i++) s += g_indeg[i];
    ssum[t] = s;
    __syncthreads();
    // Hillis-Steele inclusive scan
    for (int off = 1; off < 1024; off <<= 1) {
        int v = 0;
        if (t >= off) v = ssum[t - off];
        __syncthreads();
        if (t >= off) ssum[t] += v;
        __syncthreads();
    }
    int run = (t == 0) ? 0 : ssum[t - 1];
    for (int i = start; i < end; i++) { g_rowptr[i] = run; run += g_indeg[i]; }
    if (end == N_NODES && start < N_NODES) g_rowptr[N_NODES] = run;
}

__global__ void k_fill(const int* __restrict__ src, const int* __restrict__ dst) {
    int e = blockIdx.x * blockDim.x + threadIdx.x;
    if (e < N_EDGES) {
        int d = dst[e];
        int pos = atomicAdd(&g_cursor[d], 1);
        g_csrsrc[g_rowptr[d] + pos] = src[e];
    }
}

// g_x = h * norm_src  (row scale)
__global__ void k_scale0(const float* __restrict__ h) {
    int idx = blockIdx.x * blockDim.x + threadIdx.x;  // float4 index
    if (idx < N_NODES * DV4) {
        int row = idx >> 5;
        float s = g_ns[row];
        float4 v = ((const float4*)h)[idx];
        v.x *= s; v.y *= s; v.z *= s; v.w *= s;
        ((float4*)g_x)[idx] = v;
    }
}

// ---------------- per-layer aggregation: warp per dst node ----------------
// 4-deep edge unroll: 4 independent LDG.128 in flight per lane to cover L2 latency.
__global__ void k_aggregate() {
    int warp = (blockIdx.x * blockDim.x + threadIdx.x) >> 5;
    int lane = threadIdx.x & 31;
    if (warp >= N_NODES) return;
    int e0 = g_rowptr[warp];
    int e1 = g_rowptr[warp + 1];
    const float4* __restrict__ x4 = (const float4*)g_x;
    float4 a0 = make_float4(0.f, 0.f, 0.f, 0.f);
    float4 a1 = make_float4(0.f, 0.f, 0.f, 0.f);
    float4 a2 = make_float4(0.f, 0.f, 0.f, 0.f);
    float4 a3 = make_float4(0.f, 0.f, 0.f, 0.f);
    int j = e0;
    for (; j + 3 < e1; j += 4) {
        int s0 = __ldg(&g_csrsrc[j]);
        int s1 = __ldg(&g_csrsrc[j + 1]);
        int s2 = __ldg(&g_csrsrc[j + 2]);
        int s3 = __ldg(&g_csrsrc[j + 3]);
        float4 v0 = __ldg(&x4[s0 * DV4 + lane]);
        float4 v1 = __ldg(&x4[s1 * DV4 + lane]);
        float4 v2 = __ldg(&x4[s2 * DV4 + lane]);
        float4 v3 = __ldg(&x4[s3 * DV4 + lane]);
        a0.x += v0.x; a0.y += v0.y; a0.z += v0.z; a0.w += v0.w;
        a1.x += v1.x; a1.y += v1.y; a1.z += v1.z; a1.w += v1.w;
        a2.x += v2.x; a2.y += v2.y; a2.z += v2.z; a2.w += v2.w;
        a3.x += v3.x; a3.y += v3.y; a3.z += v3.z; a3.w += v3.w;
    }
    for (; j < e1; j++) {
        int s0 = __ldg(&g_csrsrc[j]);
        float4 v0 = __ldg(&x4[s0 * DV4 + lane]);
        a0.x += v0.x; a0.y += v0.y; a0.z += v0.z; a0.w += v0.w;
    }
    a0.x += a1.x + a2.x + a3.x;
    a0.y += a1.y + a2.y + a3.y;
    a0.z += a1.z + a2.z + a3.z;
    a0.w += a1.w + a2.w + a3.w;
    ((float4*)g_agg)[warp * DV4 + lane] = a0;
}

// ---------------- GEMM: g_x = (g_agg * c1) @ W + b * ns ----------------
// 256 threads, 64-row tile, K split into two 64 chunks. smem = 48KB exactly.
__global__ void __launch_bounds__(256) k_gemm(const float* __restrict__ W,
                                              const float* __restrict__ b) {
    __shared__ float ws[64][128];  // W[kk+r][:]
    __shared__ float as[64][64];   // scaled A tile
    int t = threadIdx.x;
    int row0 = blockIdx.x * 64;
    int tx = t & 31;       // col group: cols tx*4..tx*4+3
    int ty = t >> 5;       // row group: rows ty*8..ty*8+7
    float acc[8][4];
#pragma unroll
    for (int r = 0; r < 8; r++)
#pragma unroll
        for (int c = 0; c < 4; c++) acc[r][c] = 0.f;

    for (int kk = 0; kk < 128; kk += 64) {
        // load W chunk: 64x128 floats = 2048 float4
#pragma unroll
        for (int i = 0; i < 8; i++) {
            int idx = t + i * 256;          // float4 index 0..2047
            int r = idx >> 5;               // row (32 float4 per row)
            int c = idx & 31;
            ((float4*)ws)[idx] = ((const float4*)W)[(kk + r) * 32 + c];
        }
        // load A chunk: 64x64 floats = 1024 float4, scaled by c1[row]
#pragma unroll
        for (int i = 0; i < 4; i++) {
            int idx = t + i * 256;          // 0..1023
            int r = idx >> 4;               // row (16 float4 per row)
            int c = idx & 15;
            int grow = row0 + r;
            float4 v = make_float4(0.f, 0.f, 0.f, 0.f);
            float sc = 0.f;
            if (grow < N_NODES) {
                sc = g_c1[grow];
                v = ((const float4*)g_agg)[grow * 32 + (kk >> 2) + c];
            }
            v.x *= sc; v.y *= sc; v.z *= sc; v.w *= sc;
            ((float4*)as)[idx] = v;
        }
        __syncthreads();
#pragma unroll 8
        for (int k = 0; k < 64; k++) {
            float4 w4 = ((const float4*)ws)[k * 32 + tx];
            float a[8];
#pragma unroll
            for (int r = 0; r < 8; r++) a[r] = as[ty * 8 + r][k];
#pragma unroll
            for (int r = 0; r < 8; r++) {
                acc[r][0] += a[r] * w4.x;
                acc[r][1] += a[r] * w4.y;
                acc[r][2] += a[r] * w4.z;
                acc[r][3] += a[r] * w4.w;
            }
        }
        __syncthreads();
    }
    float4 b4 = ((const float4*)b)[tx];
#pragma unroll
    for (int r = 0; r < 8; r++) {
        int grow = row0 + ty * 8 + r;
        if (grow < N_NODES) {
            float bs = g_ns[grow];  // fold norm_src of next layer into output
            float4 o;
            o.x = acc[r][0] + b4.x * bs;
            o.y = acc[r][1] + b4.y * bs;
            o.z = acc[r][2] + b4.z * bs;
            o.w = acc[r][3] + b4.w * bs;
            ((float4*)g_x)[grow * 32 + tx] = o;
        }
    }
}

// ---------------- collapsed layer 5 ----------------
__global__ void k_w5f(const float* __restrict__ W5, const float* __restrict__ b5,
                      const float* __restrict__ fcw) {
    int j = threadIdx.x;  // 128
    float s = 0.f;
    for (int o = 0; o < D; o++) s += W5[j * D + o] * fcw[o];
    g_w5f[j] = s;
    if (j == 0) {
        float bb = 0.f;
        for (int o = 0; o < D; o++) bb += b5[o] * fcw[o];
        g_bf = bb;
    }
}

__global__ void k_p() {
    int warp = (blockIdx.x * blockDim.x + threadIdx.x) >> 5;
    int lane = threadIdx.x & 31;
    if (warp >= N_NODES) return;
    float4 v = ((const float4*)g_agg)[warp * DV4 + lane];
    float4 w = ((const float4*)g_w5f)[lane];
    float s = v.x * w.x + v.y * w.y + v.z * w.z + v.w * w.w;
#pragma unroll
    for (int o = 16; o; o >>= 1) s += __shfl_xor_sync(0xffffffffu, s, o);
    if (lane == 0) g_p[warp] = g_nd[warp] * s + g_bf;
}

// single block: segmented reduce (graph_ids are sorted) + sigmoid
__global__ void k_pool(const int* __restrict__ gids, const float* __restrict__ fcb,
                       float* __restrict__ out) {
    __shared__ float gsum[N_GRAPHS];
    __shared__ int gcnt[N_GRAPHS];
    int t = threadIdx.x;  // 1024
    if (t < N_GRAPHS) { gsum[t] = 0.f; gcnt[t] = 0; }
    __syncthreads();
    const int CH = (N_NODES + 1023) / 1024;
    int start = t * CH;
    int end = min(start + CH, N_NODES);
    if (start < end) {
        int curg = gids[start];
        float s = 0.f; int c = 0;
        for (int i = start; i < end; i++) {
            int g = gids[i];
            if (g != curg) {
                atomicAdd(&gsum[curg], s);
                atomicAdd(&gcnt[curg], c);
                curg = g; s = 0.f; c = 0;
            }
            s += g_p[i]; c++;
        }
        atomicAdd(&gsum[curg], s);
        atomicAdd(&gcnt[curg], c);
    }
    __syncthreads();
    if (t < N_GRAPHS) {
        float cnt = fmaxf((float)gcnt[t], 1.0f);
        float v = gsum[t] / cnt + fcb[0];
        out[t] = 1.0f / (1.0f + expf(-v));
    }
}

// ---------------- launch ----------------
extern "C" void kernel_launch(void* const* d_in, const int* in_sizes, int n_in,
                              void* d_out, int out_size) {
    const float* h   = (const float*)d_in[0];
    const int* src   = (const int*)d_in[1];
    const int* dst   = (const int*)d_in[2];
    const int* gids  = (const int*)d_in[3];
    const float* W1  = (const float*)d_in[4];
    const float* b1  = (const float*)d_in[5];
    const float* W2  = (const float*)d_in[6];
    const float* b2  = (const float*)d_in[7];
    const float* W3  = (const float*)d_in[8];
    const float* b3  = (const float*)d_in[9];
    const float* W4  = (const float*)d_in[10];
    const float* b4  = (const float*)d_in[11];
    const float* W5  = (const float*)d_in[12];
    const float* b5  = (const float*)d_in[13];
    const float* fcw = (const float*)d_in[14];
    const float* fcb = (const float*)d_in[15];
    float* out = (float*)d_out;

    const int TB = 256;
    k_zero<<<(N_NODES + TB - 1) / TB, TB>>>();
    k_degree<<<(N_EDGES + TB - 1) / TB, TB>>>(src, dst);
    k_norms<<<(N_NODES + TB - 1) / TB, TB>>>();
    k_scan<<<1, 1024>>>();
    k_fill<<<(N_EDGES + TB - 1) / TB, TB>>>(src, dst);
    k_scale0<<<(N_NODES * DV4 + TB - 1) / TB, TB>>>(h);
    k_w5f<<<1, 128>>>(W5, b5, fcw);

    const float* Ws[4] = {W1, W2, W3, W4};
    const float* bs[4] = {b1, b2, b3, b4};
    int aggGrid = (N_NODES * 32 + TB - 1) / TB;   // warp per node
    int gemmGrid = (N_NODES + 63) / 64;
    for (int l = 0; l < 4; l++) {
        k_aggregate<<<aggGrid, TB>>>();
        k_gemm<<<gemmGrid, TB>>>(Ws[l], bs[l]);
    }
    k_aggregate<<<aggGrid, TB>>>();
    k_p<<<aggGrid, TB>>>();
    k_pool<<<1, 1024>>>(gids, fcb, out);
}